// round 4
// baseline (speedup 1.0000x reference)
#include <cuda_runtime.h>
#include <cstdint>

#define N_NODES 50000
#define N_EDGES 800000
#define D 128
#define D4 (D / 4)
#define SCAN_T 1024

// CSR scratch + h accumulator (static device globals; no allocation).
__device__ int g_deg[N_NODES];
__device__ int g_off[N_NODES + 1];
__device__ int g_cursor[N_NODES];
__device__ int g_csr[N_EDGES];
__device__ float g_h[N_NODES * D];    // 25.6 MB

// ---------------------------------------------------------------------------
// K1: clear degree counters.
// ---------------------------------------------------------------------------
__global__ void clear_deg_kernel() {
    int i = blockIdx.x * blockDim.x + threadIdx.x;
    if (i < N_NODES) g_deg[i] = 0;
}

// ---------------------------------------------------------------------------
// K2: in-degree histogram (int4 loads, 4 REDs/thread).
// ---------------------------------------------------------------------------
__global__ void hist_kernel(const int* __restrict__ edge_dst) {
    int i = blockIdx.x * blockDim.x + threadIdx.x;
    if (i < N_EDGES / 4) {
        int4 d = reinterpret_cast<const int4*>(edge_dst)[i];
        atomicAdd(&g_deg[d.x], 1);
        atomicAdd(&g_deg[d.y], 1);
        atomicAdd(&g_deg[d.z], 1);
        atomicAdd(&g_deg[d.w], 1);
    }
}

// ---------------------------------------------------------------------------
// K3: single-block exclusive scan over degrees -> g_off, g_cursor.
// ---------------------------------------------------------------------------
__global__ void scan_kernel() {
    __shared__ int s_part[SCAN_T];
    int t = threadIdx.x;
    const int C = (N_NODES + SCAN_T - 1) / SCAN_T;   // 49
    int start = t * C;
    int end = start + C; if (end > N_NODES) end = N_NODES;

    int sum = 0;
    #pragma unroll 8
    for (int i = start; i < end; i++) sum += g_deg[i];
    s_part[t] = sum;
    __syncthreads();

    for (int d = 1; d < SCAN_T; d <<= 1) {
        int v = 0;
        if (t >= d) v = s_part[t - d];
        __syncthreads();
        if (t >= d) s_part[t] += v;
        __syncthreads();
    }

    int run = (t == 0) ? 0 : s_part[t - 1];
    for (int i = start; i < end; i++) {
        g_off[i] = run;
        g_cursor[i] = run;
        run += g_deg[i];
    }
    if (t == SCAN_T - 1) g_off[N_NODES] = s_part[SCAN_T - 1];
}

// ---------------------------------------------------------------------------
// K4: bucket fill — scatter src ids into dst's CSR segment.
// ---------------------------------------------------------------------------
__global__ void bucket_kernel(const int* __restrict__ edge_src,
                              const int* __restrict__ edge_dst) {
    int i = blockIdx.x * blockDim.x + threadIdx.x;
    if (i < N_EDGES / 4) {
        int4 d = reinterpret_cast<const int4*>(edge_dst)[i];
        int4 s = reinterpret_cast<const int4*>(edge_src)[i];
        g_csr[atomicAdd(&g_cursor[d.x], 1)] = s.x;
        g_csr[atomicAdd(&g_cursor[d.y], 1)] = s.y;
        g_csr[atomicAdd(&g_cursor[d.z], 1)] = s.z;
        g_csr[atomicAdd(&g_cursor[d.w], 1)] = s.w;
    }
}

// ---------------------------------------------------------------------------
// K5: aggregate — one warp per node, lane = float4 chunk of the row.
// 4-wide unrolled independent gathers (MLP=4), no smem, low regs -> full
// occupancy; pure L2 reads, no float atomics. Writes h to g_h.
// ---------------------------------------------------------------------------
__global__ void __launch_bounds__(256) agg_kernel(const float* __restrict__ feature) {
    int w = (blockIdx.x * blockDim.x + threadIdx.x) >> 5;
    int lane = threadIdx.x & 31;
    if (w >= N_NODES) return;

    const float4* f4 = reinterpret_cast<const float4*>(feature);
    int j  = g_off[w];
    int j1 = g_off[w + 1];

    float4 acc = make_float4(0.f, 0.f, 0.f, 0.f);
    for (; j + 4 <= j1; j += 4) {
        int s0 = g_csr[j], s1 = g_csr[j + 1], s2 = g_csr[j + 2], s3 = g_csr[j + 3];
        float4 v0 = __ldg(f4 + (size_t)s0 * D4 + lane);
        float4 v1 = __ldg(f4 + (size_t)s1 * D4 + lane);
        float4 v2 = __ldg(f4 + (size_t)s2 * D4 + lane);
        float4 v3 = __ldg(f4 + (size_t)s3 * D4 + lane);
        acc.x += v0.x + v1.x + v2.x + v3.x;
        acc.y += v0.y + v1.y + v2.y + v3.y;
        acc.z += v0.z + v1.z + v2.z + v3.z;
        acc.w += v0.w + v1.w + v2.w + v3.w;
    }
    for (; j < j1; j++) {
        int s0 = g_csr[j];
        float4 v0 = __ldg(f4 + (size_t)s0 * D4 + lane);
        acc.x += v0.x; acc.y += v0.y; acc.z += v0.z; acc.w += v0.w;
    }
    reinterpret_cast<float4*>(g_h)[(size_t)w * D4 + lane] = acc;
}

// ---------------------------------------------------------------------------
// K6: out = relu(h @ W + b). 8 warps/block, 4 rows x 128 cols per warp,
// packed fma.rn.f32x2, W L1-hot.
// ---------------------------------------------------------------------------
__global__ void gemm_bias_relu_kernel(const float* __restrict__ W,
                                      const float* __restrict__ b,
                                      float* __restrict__ out) {
    __shared__ float s_h[8][4][D];   // 16 KB

    int warp = threadIdx.x >> 5;
    int lane = threadIdx.x & 31;
    int row0 = (blockIdx.x * 8 + warp) * 4;

    const float4* h4 = reinterpret_cast<const float4*>(g_h);
    #pragma unroll
    for (int r = 0; r < 4; r++) {
        int row = row0 + r;
        float4 v = make_float4(0.f, 0.f, 0.f, 0.f);
        if (row < N_NODES) v = h4[(size_t)row * D4 + lane];
        reinterpret_cast<float4*>(&s_h[warp][r][0])[lane] = v;
    }
    __syncwarp();

    unsigned long long acc[4][2];
    #pragma unroll
    for (int r = 0; r < 4; r++) { acc[r][0] = 0ull; acc[r][1] = 0ull; }

    const float4* W4 = reinterpret_cast<const float4*>(W);
    #pragma unroll 4
    for (int k = 0; k < D; k++) {
        float4 wv = __ldg(W4 + (size_t)k * D4 + lane);
        unsigned long long w01, w23;
        asm("mov.b64 %0, {%1, %2};" : "=l"(w01) : "f"(wv.x), "f"(wv.y));
        asm("mov.b64 %0, {%1, %2};" : "=l"(w23) : "f"(wv.z), "f"(wv.w));
        #pragma unroll
        for (int r = 0; r < 4; r++) {
            float hv = s_h[warp][r][k];
            unsigned long long hh;
            asm("mov.b64 %0, {%1, %1};" : "=l"(hh) : "f"(hv));
            asm("fma.rn.f32x2 %0, %1, %2, %0;" : "+l"(acc[r][0]) : "l"(hh), "l"(w01));
            asm("fma.rn.f32x2 %0, %1, %2, %0;" : "+l"(acc[r][1]) : "l"(hh), "l"(w23));
        }
    }

    float4 bv = __ldg(reinterpret_cast<const float4*>(b) + lane);
    #pragma unroll
    for (int r = 0; r < 4; r++) {
        int row = row0 + r;
        if (row >= N_NODES) break;
        float a0, a1, a2, a3;
        asm("mov.b64 {%0, %1}, %2;" : "=f"(a0), "=f"(a1) : "l"(acc[r][0]));
        asm("mov.b64 {%0, %1}, %2;" : "=f"(a2), "=f"(a3) : "l"(acc[r][1]));
        float4 o;
        o.x = fmaxf(a0 + bv.x, 0.f);
        o.y = fmaxf(a1 + bv.y, 0.f);
        o.z = fmaxf(a2 + bv.z, 0.f);
        o.w = fmaxf(a3 + bv.w, 0.f);
        reinterpret_cast<float4*>(out)[(size_t)row * D4 + lane] = o;
    }
}

// ---------------------------------------------------------------------------
// Inputs: feature f32[50000,128], edge_src i32[800000], edge_dst i32[800000],
// W f32[128,128], b f32[128]. Output f32[50000,128].
// ---------------------------------------------------------------------------
extern "C" void kernel_launch(void* const* d_in, const int* in_sizes, int n_in,
                              void* d_out, int out_size) {
    const float* feature  = (const float*)d_in[0];
    const int*   edge_src = (const int*)d_in[1];
    const int*   edge_dst = (const int*)d_in[2];
    const float* W        = (const float*)d_in[3];
    const float* b        = (const float*)d_in[4];
    float* out = (float*)d_out;

    clear_deg_kernel<<<(N_NODES + 255) / 256, 256>>>();
    hist_kernel<<<(N_EDGES / 4 + 255) / 256, 256>>>(edge_dst);
    scan_kernel<<<1, SCAN_T>>>();
    bucket_kernel<<<(N_EDGES / 4 + 255) / 256, 256>>>(edge_src, edge_dst);
    agg_kernel<<<(N_NODES * 32 + 255) / 256, 256>>>(feature);
    gemm_bias_relu_kernel<<<(N_NODES + 31) / 32, 256>>>(W, b, out);
}

// round 5
// speedup vs baseline: 1.4677x; 1.4677x over previous
#include <cuda_runtime.h>
#include <cuda_fp16.h>
#include <cstdint>

#define N_NODES 50000
#define N_EDGES 800000
#define D 128
#define D4 (D / 4)
#define SCAN_T 1024

// Static device scratch (no allocation).
__device__ int   g_deg[N_NODES];
__device__ int   g_off[N_NODES + 1];
__device__ int   g_cursor[N_NODES];
__device__ int   g_csr[N_EDGES];
__device__ uint2 g_feat_h[N_NODES * 32];   // feature in fp16: row = 32 x uint2 = 256B
__device__ float g_h[N_NODES * D];         // aggregated h in fp32 (25.6 MB)

// ---------------------------------------------------------------------------
// K1: prep — convert feature f32 -> f16 AND clear degree counters.
// ---------------------------------------------------------------------------
__global__ void __launch_bounds__(256) prep_kernel(const float* __restrict__ feature) {
    int i = blockIdx.x * blockDim.x + threadIdx.x;
    if (i < N_NODES * D4) {
        float4 v = __ldg(reinterpret_cast<const float4*>(feature) + i);
        __half2 lo = __floats2half2_rn(v.x, v.y);
        __half2 hi = __floats2half2_rn(v.z, v.w);
        uint2 p;
        p.x = *reinterpret_cast<unsigned*>(&lo);
        p.y = *reinterpret_cast<unsigned*>(&hi);
        g_feat_h[i] = p;
    }
    if (i < N_NODES) g_deg[i] = 0;
}

// ---------------------------------------------------------------------------
// K2: in-degree histogram.
// ---------------------------------------------------------------------------
__global__ void hist_kernel(const int* __restrict__ edge_dst) {
    int i = blockIdx.x * blockDim.x + threadIdx.x;
    if (i < N_EDGES / 4) {
        int4 d = reinterpret_cast<const int4*>(edge_dst)[i];
        atomicAdd(&g_deg[d.x], 1);
        atomicAdd(&g_deg[d.y], 1);
        atomicAdd(&g_deg[d.z], 1);
        atomicAdd(&g_deg[d.w], 1);
    }
}

// ---------------------------------------------------------------------------
// K3: single-block exclusive scan -> g_off, g_cursor.
// ---------------------------------------------------------------------------
__global__ void scan_kernel() {
    __shared__ int s_part[SCAN_T];
    int t = threadIdx.x;
    const int C = (N_NODES + SCAN_T - 1) / SCAN_T;   // 49
    int start = t * C;
    int end = start + C; if (end > N_NODES) end = N_NODES;

    int sum = 0;
    #pragma unroll 8
    for (int i = start; i < end; i++) sum += g_deg[i];
    s_part[t] = sum;
    __syncthreads();

    for (int d = 1; d < SCAN_T; d <<= 1) {
        int v = 0;
        if (t >= d) v = s_part[t - d];
        __syncthreads();
        if (t >= d) s_part[t] += v;
        __syncthreads();
    }

    int run = (t == 0) ? 0 : s_part[t - 1];
    for (int i = start; i < end; i++) {
        g_off[i] = run;
        g_cursor[i] = run;
        run += g_deg[i];
    }
    if (t == SCAN_T - 1) g_off[N_NODES] = s_part[SCAN_T - 1];
}

// ---------------------------------------------------------------------------
// K4: bucket fill — scatter src ids into dst's CSR segment.
// ---------------------------------------------------------------------------
__global__ void bucket_kernel(const int* __restrict__ edge_src,
                              const int* __restrict__ edge_dst) {
    int i = blockIdx.x * blockDim.x + threadIdx.x;
    if (i < N_EDGES / 4) {
        int4 d = reinterpret_cast<const int4*>(edge_dst)[i];
        int4 s = reinterpret_cast<const int4*>(edge_src)[i];
        g_csr[atomicAdd(&g_cursor[d.x], 1)] = s.x;
        g_csr[atomicAdd(&g_cursor[d.y], 1)] = s.y;
        g_csr[atomicAdd(&g_cursor[d.z], 1)] = s.z;
        g_csr[atomicAdd(&g_cursor[d.w], 1)] = s.w;
    }
}

// ---------------------------------------------------------------------------
// K5: aggregate — one warp per node. CSR indices for the chain are loaded with
// ONE coalesced warp-wide load and broadcast via shfl, so every f16 feature
// gather is independent (no index->gather dependency level). fp32 accumulate,
// fp32 h written out.
// ---------------------------------------------------------------------------
__device__ __forceinline__ void acc_row(float4& acc, uint2 a) {
    __half2 lo = *reinterpret_cast<__half2*>(&a.x);
    __half2 hi = *reinterpret_cast<__half2*>(&a.y);
    float2 f0 = __half22float2(lo);
    float2 f1 = __half22float2(hi);
    acc.x += f0.x; acc.y += f0.y; acc.z += f1.x; acc.w += f1.y;
}

__global__ void __launch_bounds__(256) agg_kernel() {
    int w = (blockIdx.x * blockDim.x + threadIdx.x) >> 5;
    int lane = threadIdx.x & 31;
    if (w >= N_NODES) return;

    int j0 = g_off[w];
    int len = g_off[w + 1] - j0;

    const uint2* fh = g_feat_h;
    float4 acc = make_float4(0.f, 0.f, 0.f, 0.f);

    for (int base = 0; base < len; base += 32) {
        int nb = len - base; if (nb > 32) nb = 32;
        int myidx = 0;
        if (base + lane < len) myidx = g_csr[j0 + base + lane];   // coalesced

        int t = 0;
        for (; t + 4 <= nb; t += 4) {
            int s0 = __shfl_sync(0xffffffffu, myidx, t);
            int s1 = __shfl_sync(0xffffffffu, myidx, t + 1);
            int s2 = __shfl_sync(0xffffffffu, myidx, t + 2);
            int s3 = __shfl_sync(0xffffffffu, myidx, t + 3);
            uint2 a0 = __ldg(fh + (size_t)s0 * 32 + lane);
            uint2 a1 = __ldg(fh + (size_t)s1 * 32 + lane);
            uint2 a2 = __ldg(fh + (size_t)s2 * 32 + lane);
            uint2 a3 = __ldg(fh + (size_t)s3 * 32 + lane);
            acc_row(acc, a0); acc_row(acc, a1); acc_row(acc, a2); acc_row(acc, a3);
        }
        for (; t < nb; t++) {
            int s0 = __shfl_sync(0xffffffffu, myidx, t);
            uint2 a0 = __ldg(fh + (size_t)s0 * 32 + lane);
            acc_row(acc, a0);
        }
    }
    reinterpret_cast<float4*>(g_h)[(size_t)w * D4 + lane] = acc;
}

// ---------------------------------------------------------------------------
// K6: out = relu(h @ W + b). 8 warps/block, 8 rows per warp.
// h staged transposed in smem (s[k*10 + r], pad 10 keeps LDS.64 8B-aligned);
// row PAIRS packed into f32x2 accumulators: one LDS.64 broadcast fetches
// {h[r], h[r+1]} at column k with zero packing movs. 16 FMA2 per k-iter.
// ---------------------------------------------------------------------------
__global__ void __launch_bounds__(256) gemm_kernel(const float* __restrict__ W,
                                                   const float* __restrict__ b,
                                                   float* __restrict__ out) {
    __shared__ float s_h[8][D * 10];   // 40 KB total

    int warp = threadIdx.x >> 5;
    int lane = threadIdx.x & 31;
    int row0 = (blockIdx.x * 8 + warp) * 8;
    float* s = s_h[warp];

    // Stage 8 rows, transposed: s[k*10 + r] = h[row0+r][k].
    const float4* h4 = reinterpret_cast<const float4*>(g_h);
    #pragma unroll
    for (int r = 0; r < 8; r++) {
        int row = row0 + r;
        float4 v = make_float4(0.f, 0.f, 0.f, 0.f);
        if (row < N_NODES) v = h4[(size_t)row * D4 + lane];
        int k0 = lane * 4;
        s[(k0 + 0) * 10 + r] = v.x;
        s[(k0 + 1) * 10 + r] = v.y;
        s[(k0 + 2) * 10 + r] = v.z;
        s[(k0 + 3) * 10 + r] = v.w;
    }
    __syncwarp();

    // acc[pair][col] = f32x2 {row 2p, row 2p+1} for output col 4*lane+c.
    unsigned long long acc[4][4];
    #pragma unroll
    for (int p = 0; p < 4; p++)
        #pragma unroll
        for (int c = 0; c < 4; c++) acc[p][c] = 0ull;

    const float4* W4 = reinterpret_cast<const float4*>(W);
    #pragma unroll 4
    for (int k = 0; k < D; k++) {
        float4 wv = __ldg(W4 + (size_t)k * D4 + lane);
        unsigned long long wd[4];
        asm("mov.b64 %0, {%1, %1};" : "=l"(wd[0]) : "f"(wv.x));
        asm("mov.b64 %0, {%1, %1};" : "=l"(wd[1]) : "f"(wv.y));
        asm("mov.b64 %0, {%1, %1};" : "=l"(wd[2]) : "f"(wv.z));
        asm("mov.b64 %0, {%1, %1};" : "=l"(wd[3]) : "f"(wv.w));
        const float* sk = s + k * 10;
        #pragma unroll
        for (int p = 0; p < 4; p++) {
            unsigned long long hp = *reinterpret_cast<const unsigned long long*>(sk + 2 * p);
            asm("fma.rn.f32x2 %0, %1, %2, %0;" : "+l"(acc[p][0]) : "l"(hp), "l"(wd[0]));
            asm("fma.rn.f32x2 %0, %1, %2, %0;" : "+l"(acc[p][1]) : "l"(hp), "l"(wd[1]));
            asm("fma.rn.f32x2 %0, %1, %2, %0;" : "+l"(acc[p][2]) : "l"(hp), "l"(wd[2]));
            asm("fma.rn.f32x2 %0, %1, %2, %0;" : "+l"(acc[p][3]) : "l"(hp), "l"(wd[3]));
        }
    }

    float4 bv = __ldg(reinterpret_cast<const float4*>(b) + lane);
    #pragma unroll
    for (int p = 0; p < 4; p++) {
        float lo[4], hi[4];
        #pragma unroll
        for (int c = 0; c < 4; c++)
            asm("mov.b64 {%0, %1}, %2;" : "=f"(lo[c]), "=f"(hi[c]) : "l"(acc[p][c]));
        int r0 = row0 + 2 * p;
        if (r0 < N_NODES) {
            float4 o;
            o.x = fmaxf(lo[0] + bv.x, 0.f);
            o.y = fmaxf(lo[1] + bv.y, 0.f);
            o.z = fmaxf(lo[2] + bv.z, 0.f);
            o.w = fmaxf(lo[3] + bv.w, 0.f);
            reinterpret_cast<float4*>(out)[(size_t)r0 * D4 + lane] = o;
        }
        if (r0 + 1 < N_NODES) {
            float4 o;
            o.x = fmaxf(hi[0] + bv.x, 0.f);
            o.y = fmaxf(hi[1] + bv.y, 0.f);
            o.z = fmaxf(hi[2] + bv.z, 0.f);
            o.w = fmaxf(hi[3] + bv.w, 0.f);
            reinterpret_cast<float4*>(out)[(size_t)(r0 + 1) * D4 + lane] = o;
        }
    }
}

// ---------------------------------------------------------------------------
// Inputs: feature f32[50000,128], edge_src i32[800000], edge_dst i32[800000],
// W f32[128,128], b f32[128]. Output f32[50000,128].
// ---------------------------------------------------------------------------
extern "C" void kernel_launch(void* const* d_in, const int* in_sizes, int n_in,
                              void* d_out, int out_size) {
    const float* feature  = (const float*)d_in[0];
    const int*   edge_src = (const int*)d_in[1];
    const int*   edge_dst = (const int*)d_in[2];
    const float* W        = (const float*)d_in[3];
    const float* b        = (const float*)d_in[4];
    float* out = (float*)d_out;

    prep_kernel<<<(N_NODES * D4 + 255) / 256, 256>>>(feature);
    hist_kernel<<<(N_EDGES / 4 + 255) / 256, 256>>>(edge_dst);
    scan_kernel<<<1, SCAN_T>>>();
    bucket_kernel<<<(N_EDGES / 4 + 255) / 256, 256>>>(edge_src, edge_dst);
    agg_kernel<<<(N_NODES * 32 + 255) / 256, 256>>>();
    gemm_kernel<<<(N_NODES + 63) / 64, 256>>>(W, b, out);
}

// round 6
// speedup vs baseline: 1.4701x; 1.0016x over previous
#include <cuda_runtime.h>
#include <cuda_fp16.h>
#include <cstdint>

#define N_NODES 50000
#define N_EDGES 800000
#define D 128
#define D4 (D / 4)
#define SCAN_T 1024
#define FULL 0xffffffffu

// Static device scratch (no allocation; zero-initialized at load).
__device__ int   g_deg[N_NODES];
__device__ int   g_off[N_NODES + 1];
__device__ int   g_cursor[N_NODES];
__device__ int   g_csr[N_EDGES];
__device__ uint2 g_feat_h[N_NODES * 32];   // fp16 feature: row = 256B
__device__ float g_h[N_NODES * D];         // fp32 aggregate
__device__ uint4 g_zero16[16];             // 256B of zeros, never written

// ---------------------------------------------------------------------------
// K1: prep — feature f32 -> f16, and clear degree counters.
// ---------------------------------------------------------------------------
__global__ void __launch_bounds__(256) prep_kernel(const float* __restrict__ feature) {
    int i = blockIdx.x * blockDim.x + threadIdx.x;
    if (i < N_NODES * D4) {
        float4 v = __ldg(reinterpret_cast<const float4*>(feature) + i);
        __half2 lo = __floats2half2_rn(v.x, v.y);
        __half2 hi = __floats2half2_rn(v.z, v.w);
        uint2 p;
        p.x = *reinterpret_cast<unsigned*>(&lo);
        p.y = *reinterpret_cast<unsigned*>(&hi);
        g_feat_h[i] = p;
    }
    if (i < N_NODES) g_deg[i] = 0;
}

// ---------------------------------------------------------------------------
// K2: in-degree histogram.
// ---------------------------------------------------------------------------
__global__ void hist_kernel(const int* __restrict__ edge_dst) {
    int i = blockIdx.x * blockDim.x + threadIdx.x;
    if (i < N_EDGES / 4) {
        int4 d = reinterpret_cast<const int4*>(edge_dst)[i];
        atomicAdd(&g_deg[d.x], 1);
        atomicAdd(&g_deg[d.y], 1);
        atomicAdd(&g_deg[d.z], 1);
        atomicAdd(&g_deg[d.w], 1);
    }
}

// ---------------------------------------------------------------------------
// K3: single-block exclusive scan -> g_off, g_cursor.
// ---------------------------------------------------------------------------
__global__ void scan_kernel() {
    __shared__ int s_part[SCAN_T];
    int t = threadIdx.x;
    const int C = (N_NODES + SCAN_T - 1) / SCAN_T;   // 49
    int start = t * C;
    int end = start + C; if (end > N_NODES) end = N_NODES;

    int sum = 0;
    #pragma unroll 8
    for (int i = start; i < end; i++) sum += g_deg[i];
    s_part[t] = sum;
    __syncthreads();

    for (int d = 1; d < SCAN_T; d <<= 1) {
        int v = 0;
        if (t >= d) v = s_part[t - d];
        __syncthreads();
        if (t >= d) s_part[t] += v;
        __syncthreads();
    }

    int run = (t == 0) ? 0 : s_part[t - 1];
    for (int i = start; i < end; i++) {
        g_off[i] = run;
        g_cursor[i] = run;
        run += g_deg[i];
    }
    if (t == SCAN_T - 1) g_off[N_NODES] = s_part[SCAN_T - 1];
}

// ---------------------------------------------------------------------------
// K4: bucket fill.
// ---------------------------------------------------------------------------
__global__ void bucket_kernel(const int* __restrict__ edge_src,
                              const int* __restrict__ edge_dst) {
    int i = blockIdx.x * blockDim.x + threadIdx.x;
    if (i < N_EDGES / 4) {
        int4 d = reinterpret_cast<const int4*>(edge_dst)[i];
        int4 s = reinterpret_cast<const int4*>(edge_src)[i];
        g_csr[atomicAdd(&g_cursor[d.x], 1)] = s.x;
        g_csr[atomicAdd(&g_cursor[d.y], 1)] = s.y;
        g_csr[atomicAdd(&g_cursor[d.z], 1)] = s.z;
        g_csr[atomicAdd(&g_cursor[d.w], 1)] = s.w;
    }
}

// ---------------------------------------------------------------------------
// K5: aggregate v3 — one warp per node, HALF-warp per gathered row.
// Row = 256B fp16 = 16 lanes x uint4, so one LDG.128 fetches TWO edges' rows.
// 8-edge unrolled body keeps 4 independent LDG.128 (16 lines) in flight.
// Halves combined with shfl_xor(16); odd tail reads a static zero row.
// ---------------------------------------------------------------------------
__device__ __forceinline__ void acc8(float* acc, uint4 a) {
    float2 f0 = __half22float2(*reinterpret_cast<__half2*>(&a.x));
    float2 f1 = __half22float2(*reinterpret_cast<__half2*>(&a.y));
    float2 f2 = __half22float2(*reinterpret_cast<__half2*>(&a.z));
    float2 f3 = __half22float2(*reinterpret_cast<__half2*>(&a.w));
    acc[0] += f0.x; acc[1] += f0.y; acc[2] += f1.x; acc[3] += f1.y;
    acc[4] += f2.x; acc[5] += f2.y; acc[6] += f3.x; acc[7] += f3.y;
}

__global__ void __launch_bounds__(256) agg_kernel() {
    int w = (blockIdx.x * blockDim.x + threadIdx.x) >> 5;
    int lane = threadIdx.x & 31;
    if (w >= N_NODES) return;
    int half = lane >> 4;     // which edge of the pair this lane serves
    int hl   = lane & 15;     // 16B chunk within the row

    int j0 = g_off[w];
    int len = g_off[w + 1] - j0;

    const uint4* fh = reinterpret_cast<const uint4*>(g_feat_h);  // 16 uint4/row
    float acc[8];
    #pragma unroll
    for (int i = 0; i < 8; i++) acc[i] = 0.f;

    for (int base = 0; base < len; base += 32) {
        int nb = len - base; if (nb > 32) nb = 32;
        int myidx = 0;
        if (base + lane < len) myidx = g_csr[j0 + base + lane];   // coalesced

        int t = 0;
        // 4 independent LDG.128 in flight = 8 edges per unrolled body.
        for (; t + 8 <= nb; t += 8) {
            int s0 = __shfl_sync(FULL, myidx, t + 0 + half);
            int s1 = __shfl_sync(FULL, myidx, t + 2 + half);
            int s2 = __shfl_sync(FULL, myidx, t + 4 + half);
            int s3 = __shfl_sync(FULL, myidx, t + 6 + half);
            uint4 a0 = __ldg(fh + (size_t)s0 * 16 + hl);
            uint4 a1 = __ldg(fh + (size_t)s1 * 16 + hl);
            uint4 a2 = __ldg(fh + (size_t)s2 * 16 + hl);
            uint4 a3 = __ldg(fh + (size_t)s3 * 16 + hl);
            acc8(acc, a0); acc8(acc, a1); acc8(acc, a2); acc8(acc, a3);
        }
        for (; t + 2 <= nb; t += 2) {
            int s0 = __shfl_sync(FULL, myidx, t + half);
            uint4 a0 = __ldg(fh + (size_t)s0 * 16 + hl);
            acc8(acc, a0);
        }
        if (t < nb) {   // odd tail: lanes 16-31 read the zero row (exact no-op)
            int s0 = __shfl_sync(FULL, myidx, t);
            const uint4* p = half ? (const uint4*)g_zero16 : (fh + (size_t)s0 * 16);
            uint4 a0 = __ldg(p + hl);
            acc8(acc, a0);
        }
    }

    // Combine the two half-warp partials.
    #pragma unroll
    for (int i = 0; i < 8; i++)
        acc[i] += __shfl_xor_sync(FULL, acc[i], 16);

    if (half == 0) {
        float4* hout = reinterpret_cast<float4*>(g_h) + (size_t)w * D4 + hl * 2;
        hout[0] = make_float4(acc[0], acc[1], acc[2], acc[3]);
        hout[1] = make_float4(acc[4], acc[5], acc[6], acc[7]);
    }
}

// ---------------------------------------------------------------------------
// K6: out = relu(h @ W + b). 8 rows/warp, row-pair-packed f32x2 accumulators.
// ---------------------------------------------------------------------------
__global__ void __launch_bounds__(256) gemm_kernel(const float* __restrict__ W,
                                                   const float* __restrict__ b,
                                                   float* __restrict__ out) {
    __shared__ float s_h[8][D * 10];   // 40 KB

    int warp = threadIdx.x >> 5;
    int lane = threadIdx.x & 31;
    int row0 = (blockIdx.x * 8 + warp) * 8;
    float* s = s_h[warp];

    const float4* h4 = reinterpret_cast<const float4*>(g_h);
    #pragma unroll
    for (int r = 0; r < 8; r++) {
        int row = row0 + r;
        float4 v = make_float4(0.f, 0.f, 0.f, 0.f);
        if (row < N_NODES) v = h4[(size_t)row * D4 + lane];
        int k0 = lane * 4;
        s[(k0 + 0) * 10 + r] = v.x;
        s[(k0 + 1) * 10 + r] = v.y;
        s[(k0 + 2) * 10 + r] = v.z;
        s[(k0 + 3) * 10 + r] = v.w;
    }
    __syncwarp();

    unsigned long long acc[4][4];
    #pragma unroll
    for (int p = 0; p < 4; p++)
        #pragma unroll
        for (int c = 0; c < 4; c++) acc[p][c] = 0ull;

    const float4* W4 = reinterpret_cast<const float4*>(W);
    #pragma unroll 4
    for (int k = 0; k < D; k++) {
        float4 wv = __ldg(W4 + (size_t)k * D4 + lane);
        unsigned long long wd[4];
        asm("mov.b64 %0, {%1, %1};" : "=l"(wd[0]) : "f"(wv.x));
        asm("mov.b64 %0, {%1, %1};" : "=l"(wd[1]) : "f"(wv.y));
        asm("mov.b64 %0, {%1, %1};" : "=l"(wd[2]) : "f"(wv.z));
        asm("mov.b64 %0, {%1, %1};" : "=l"(wd[3]) : "f"(wv.w));
        const float* sk = s + k * 10;
        #pragma unroll
        for (int p = 0; p < 4; p++) {
            unsigned long long hp = *reinterpret_cast<const unsigned long long*>(sk + 2 * p);
            asm("fma.rn.f32x2 %0, %1, %2, %0;" : "+l"(acc[p][0]) : "l"(hp), "l"(wd[0]));
            asm("fma.rn.f32x2 %0, %1, %2, %0;" : "+l"(acc[p][1]) : "l"(hp), "l"(wd[1]));
            asm("fma.rn.f32x2 %0, %1, %2, %0;" : "+l"(acc[p][2]) : "l"(hp), "l"(wd[2]));
            asm("fma.rn.f32x2 %0, %1, %2, %0;" : "+l"(acc[p][3]) : "l"(hp), "l"(wd[3]));
        }
    }

    float4 bv = __ldg(reinterpret_cast<const float4*>(b) + lane);
    #pragma unroll
    for (int p = 0; p < 4; p++) {
        float lo[4], hi[4];
        #pragma unroll
        for (int c = 0; c < 4; c++)
            asm("mov.b64 {%0, %1}, %2;" : "=f"(lo[c]), "=f"(hi[c]) : "l"(acc[p][c]));
        int r0 = row0 + 2 * p;
        if (r0 < N_NODES) {
            float4 o;
            o.x = fmaxf(lo[0] + bv.x, 0.f);
            o.y = fmaxf(lo[1] + bv.y, 0.f);
            o.z = fmaxf(lo[2] + bv.z, 0.f);
            o.w = fmaxf(lo[3] + bv.w, 0.f);
            reinterpret_cast<float4*>(out)[(size_t)r0 * D4 + lane] = o;
        }
        if (r0 + 1 < N_NODES) {
            float4 o;
            o.x = fmaxf(hi[0] + bv.x, 0.f);
            o.y = fmaxf(hi[1] + bv.y, 0.f);
            o.z = fmaxf(hi[2] + bv.z, 0.f);
            o.w = fmaxf(hi[3] + bv.w, 0.f);
            reinterpret_cast<float4*>(out)[(size_t)(r0 + 1) * D4 + lane] = o;
        }
    }
}

// ---------------------------------------------------------------------------
// Inputs: feature f32[50000,128], edge_src i32[800000], edge_dst i32[800000],
// W f32[128,128], b f32[128]. Output f32[50000,128].
// ---------------------------------------------------------------------------
extern "C" void kernel_launch(void* const* d_in, const int* in_sizes, int n_in,
                              void* d_out, int out_size) {
    const float* feature  = (const float*)d_in[0];
    const int*   edge_src = (const int*)d_in[1];
    const int*   edge_dst = (const int*)d_in[2];
    const float* W        = (const float*)d_in[3];
    const float* b        = (const float*)d_in[4];
    float* out = (float*)d_out;

    prep_kernel<<<(N_NODES * D4 + 255) / 256, 256>>>(feature);
    hist_kernel<<<(N_EDGES / 4 + 255) / 256, 256>>>(edge_dst);
    scan_kernel<<<1, SCAN_T>>>();
    bucket_kernel<<<(N_EDGES / 4 + 255) / 256, 256>>>(edge_src, edge_dst);
    agg_kernel<<<(N_NODES * 32 + 255) / 256, 256>>>();
    gemm_kernel<<<(N_NODES + 63) / 64, 256>>>(W, b, out);
}

// round 7
// speedup vs baseline: 2.4321x; 1.6544x over previous
#include <cuda_runtime.h>
#include <cuda_fp16.h>
#include <cstdint>

#define N_NODES 50000
#define N_EDGES 800000
#define D 128
#define D4 (D / 4)
#define FULL 0xffffffffu
#define SCAN_B 1024
#define N_BLKS ((N_NODES + SCAN_B - 1) / SCAN_B)   // 49

// Static device scratch (no allocation; zero-initialized at load).
__device__ int   g_deg[N_NODES];
__device__ int   g_off[N_NODES + 1];
__device__ int   g_cursor[N_NODES];
__device__ int   g_csr[N_EDGES];
__device__ int   g_blk[64];                // per-block sums (padded)
__device__ int   g_blkoff[64];             // exclusive scan of block sums
__device__ uint2 g_feat_h[N_NODES * 32];   // fp16 feature: row = 256B
__device__ float g_h[N_NODES * D];         // fp32 aggregate
__device__ uint4 g_zero16[16];             // 256B of zeros, never written

// ---------------------------------------------------------------------------
// K1: prep — feature f32 -> f16, and clear degree counters.
// ---------------------------------------------------------------------------
__global__ void __launch_bounds__(256) prep_kernel(const float* __restrict__ feature) {
    int i = blockIdx.x * blockDim.x + threadIdx.x;
    if (i < N_NODES * D4) {
        float4 v = __ldg(reinterpret_cast<const float4*>(feature) + i);
        __half2 lo = __floats2half2_rn(v.x, v.y);
        __half2 hi = __floats2half2_rn(v.z, v.w);
        uint2 p;
        p.x = *reinterpret_cast<unsigned*>(&lo);
        p.y = *reinterpret_cast<unsigned*>(&hi);
        g_feat_h[i] = p;
    }
    if (i < N_NODES) g_deg[i] = 0;
}

// ---------------------------------------------------------------------------
// K2: in-degree histogram.
// ---------------------------------------------------------------------------
__global__ void hist_kernel(const int* __restrict__ edge_dst) {
    int i = blockIdx.x * blockDim.x + threadIdx.x;
    if (i < N_EDGES / 4) {
        int4 d = reinterpret_cast<const int4*>(edge_dst)[i];
        atomicAdd(&g_deg[d.x], 1);
        atomicAdd(&g_deg[d.y], 1);
        atomicAdd(&g_deg[d.z], 1);
        atomicAdd(&g_deg[d.w], 1);
    }
}

// ---------------------------------------------------------------------------
// K3a: per-block exclusive scan (coalesced). 1024 elements per block.
// Writes element-wise exclusive-within-block to g_off, block total to g_blk.
// ---------------------------------------------------------------------------
__global__ void __launch_bounds__(SCAN_B) scan1_kernel() {
    __shared__ int s_wsum[32];
    int t = threadIdx.x, wid = t >> 5, lane = t & 31;
    int i = blockIdx.x * SCAN_B + t;
    int v = (i < N_NODES) ? g_deg[i] : 0;

    // inclusive warp scan
    int x = v;
    #pragma unroll
    for (int d = 1; d < 32; d <<= 1) {
        int y = __shfl_up_sync(FULL, x, d);
        if (lane >= d) x += y;
    }
    if (lane == 31) s_wsum[wid] = x;
    __syncthreads();
    if (wid == 0) {
        int w = s_wsum[lane];
        int xx = w;
        #pragma unroll
        for (int d = 1; d < 32; d <<= 1) {
            int y = __shfl_up_sync(FULL, xx, d);
            if (lane >= d) xx += y;
        }
        s_wsum[lane] = xx - w;   // exclusive
        if (lane == 31) g_blk[blockIdx.x] = xx;   // block total
    }
    __syncthreads();

    if (i < N_NODES) g_off[i] = (x - v) + s_wsum[wid];
}

// ---------------------------------------------------------------------------
// K3b: scan the 49 block totals (single tiny block).
// ---------------------------------------------------------------------------
__global__ void scan2_kernel() {
    __shared__ int s[64];
    int t = threadIdx.x;
    s[t] = (t < N_BLKS) ? g_blk[t] : 0;
    __syncthreads();
    for (int d = 1; d < 64; d <<= 1) {
        int v = (t >= d) ? s[t - d] : 0;
        __syncthreads();
        s[t] += v;
        __syncthreads();
    }
    g_blkoff[t] = (t == 0) ? 0 : s[t - 1];   // exclusive
}

// ---------------------------------------------------------------------------
// K3c: add block offsets, init cursors (coalesced).
// ---------------------------------------------------------------------------
__global__ void __launch_bounds__(SCAN_B) scan3_kernel() {
    int i = blockIdx.x * SCAN_B + threadIdx.x;
    if (i < N_NODES) {
        int off = g_off[i] + g_blkoff[blockIdx.x];
        g_off[i] = off;
        g_cursor[i] = off;
    }
    if (i == 0) g_off[N_NODES] = N_EDGES;   // sum of degrees is known
}

// ---------------------------------------------------------------------------
// K4: bucket fill.
// ---------------------------------------------------------------------------
__global__ void bucket_kernel(const int* __restrict__ edge_src,
                              const int* __restrict__ edge_dst) {
    int i = blockIdx.x * blockDim.x + threadIdx.x;
    if (i < N_EDGES / 4) {
        int4 d = reinterpret_cast<const int4*>(edge_dst)[i];
        int4 s = reinterpret_cast<const int4*>(edge_src)[i];
        g_csr[atomicAdd(&g_cursor[d.x], 1)] = s.x;
        g_csr[atomicAdd(&g_cursor[d.y], 1)] = s.y;
        g_csr[atomicAdd(&g_cursor[d.z], 1)] = s.z;
        g_csr[atomicAdd(&g_cursor[d.w], 1)] = s.w;
    }
}

// ---------------------------------------------------------------------------
// K5: aggregate — one warp per node, half-warp per gathered fp16 row.
// ---------------------------------------------------------------------------
__device__ __forceinline__ void acc8(float* acc, uint4 a) {
    float2 f0 = __half22float2(*reinterpret_cast<__half2*>(&a.x));
    float2 f1 = __half22float2(*reinterpret_cast<__half2*>(&a.y));
    float2 f2 = __half22float2(*reinterpret_cast<__half2*>(&a.z));
    float2 f3 = __half22float2(*reinterpret_cast<__half2*>(&a.w));
    acc[0] += f0.x; acc[1] += f0.y; acc[2] += f1.x; acc[3] += f1.y;
    acc[4] += f2.x; acc[5] += f2.y; acc[6] += f3.x; acc[7] += f3.y;
}

__global__ void __launch_bounds__(256) agg_kernel() {
    int w = (blockIdx.x * blockDim.x + threadIdx.x) >> 5;
    int lane = threadIdx.x & 31;
    if (w >= N_NODES) return;
    int half = lane >> 4;
    int hl   = lane & 15;

    int j0 = g_off[w];
    int len = g_off[w + 1] - j0;

    const uint4* fh = reinterpret_cast<const uint4*>(g_feat_h);
    float acc[8];
    #pragma unroll
    for (int i = 0; i < 8; i++) acc[i] = 0.f;

    for (int base = 0; base < len; base += 32) {
        int nb = len - base; if (nb > 32) nb = 32;
        int myidx = 0;
        if (base + lane < len) myidx = g_csr[j0 + base + lane];

        int t = 0;
        for (; t + 8 <= nb; t += 8) {
            int s0 = __shfl_sync(FULL, myidx, t + 0 + half);
            int s1 = __shfl_sync(FULL, myidx, t + 2 + half);
            int s2 = __shfl_sync(FULL, myidx, t + 4 + half);
            int s3 = __shfl_sync(FULL, myidx, t + 6 + half);
            uint4 a0 = __ldg(fh + (size_t)s0 * 16 + hl);
            uint4 a1 = __ldg(fh + (size_t)s1 * 16 + hl);
            uint4 a2 = __ldg(fh + (size_t)s2 * 16 + hl);
            uint4 a3 = __ldg(fh + (size_t)s3 * 16 + hl);
            acc8(acc, a0); acc8(acc, a1); acc8(acc, a2); acc8(acc, a3);
        }
        for (; t + 2 <= nb; t += 2) {
            int s0 = __shfl_sync(FULL, myidx, t + half);
            uint4 a0 = __ldg(fh + (size_t)s0 * 16 + hl);
            acc8(acc, a0);
        }
        if (t < nb) {
            int s0 = __shfl_sync(FULL, myidx, t);
            const uint4* p = half ? (const uint4*)g_zero16 : (fh + (size_t)s0 * 16);
            uint4 a0 = __ldg(p + hl);
            acc8(acc, a0);
        }
    }

    #pragma unroll
    for (int i = 0; i < 8; i++)
        acc[i] += __shfl_xor_sync(FULL, acc[i], 16);

    if (half == 0) {
        float4* hout = reinterpret_cast<float4*>(g_h) + (size_t)w * D4 + hl * 2;
        hout[0] = make_float4(acc[0], acc[1], acc[2], acc[3]);
        hout[1] = make_float4(acc[4], acc[5], acc[6], acc[7]);
    }
}

// ---------------------------------------------------------------------------
// K6: out = relu(h @ W + b). 8 rows/warp, row-pair-packed f32x2 accumulators.
// ---------------------------------------------------------------------------
__global__ void __launch_bounds__(256) gemm_kernel(const float* __restrict__ W,
                                                   const float* __restrict__ b,
                                                   float* __restrict__ out) {
    __shared__ float s_h[8][D * 10];   // 40 KB

    int warp = threadIdx.x >> 5;
    int lane = threadIdx.x & 31;
    int row0 = (blockIdx.x * 8 + warp) * 8;
    float* s = s_h[warp];

    const float4* h4 = reinterpret_cast<const float4*>(g_h);
    #pragma unroll
    for (int r = 0; r < 8; r++) {
        int row = row0 + r;
        float4 v = make_float4(0.f, 0.f, 0.f, 0.f);
        if (row < N_NODES) v = h4[(size_t)row * D4 + lane];
        int k0 = lane * 4;
        s[(k0 + 0) * 10 + r] = v.x;
        s[(k0 + 1) * 10 + r] = v.y;
        s[(k0 + 2) * 10 + r] = v.z;
        s[(k0 + 3) * 10 + r] = v.w;
    }
    __syncwarp();

    unsigned long long acc[4][4];
    #pragma unroll
    for (int p = 0; p < 4; p++)
        #pragma unroll
        for (int c = 0; c < 4; c++) acc[p][c] = 0ull;

    const float4* W4 = reinterpret_cast<const float4*>(W);
    #pragma unroll 4
    for (int k = 0; k < D; k++) {
        float4 wv = __ldg(W4 + (size_t)k * D4 + lane);
        unsigned long long wd[4];
        asm("mov.b64 %0, {%1, %1};" : "=l"(wd[0]) : "f"(wv.x));
        asm("mov.b64 %0, {%1, %1};" : "=l"(wd[1]) : "f"(wv.y));
        asm("mov.b64 %0, {%1, %1};" : "=l"(wd[2]) : "f"(wv.z));
        asm("mov.b64 %0, {%1, %1};" : "=l"(wd[3]) : "f"(wv.w));
        const float* sk = s + k * 10;
        #pragma unroll
        for (int p = 0; p < 4; p++) {
            unsigned long long hp = *reinterpret_cast<const unsigned long long*>(sk + 2 * p);
            asm("fma.rn.f32x2 %0, %1, %2, %0;" : "+l"(acc[p][0]) : "l"(hp), "l"(wd[0]));
            asm("fma.rn.f32x2 %0, %1, %2, %0;" : "+l"(acc[p][1]) : "l"(hp), "l"(wd[1]));
            asm("fma.rn.f32x2 %0, %1, %2, %0;" : "+l"(acc[p][2]) : "l"(hp), "l"(wd[2]));
            asm("fma.rn.f32x2 %0, %1, %2, %0;" : "+l"(acc[p][3]) : "l"(hp), "l"(wd[3]));
        }
    }

    float4 bv = __ldg(reinterpret_cast<const float4*>(b) + lane);
    #pragma unroll
    for (int p = 0; p < 4; p++) {
        float lo[4], hi[4];
        #pragma unroll
        for (int c = 0; c < 4; c++)
            asm("mov.b64 {%0, %1}, %2;" : "=f"(lo[c]), "=f"(hi[c]) : "l"(acc[p][c]));
        int r0 = row0 + 2 * p;
        if (r0 < N_NODES) {
            float4 o;
            o.x = fmaxf(lo[0] + bv.x, 0.f);
            o.y = fmaxf(lo[1] + bv.y, 0.f);
            o.z = fmaxf(lo[2] + bv.z, 0.f);
            o.w = fmaxf(lo[3] + bv.w, 0.f);
            reinterpret_cast<float4*>(out)[(size_t)r0 * D4 + lane] = o;
        }
        if (r0 + 1 < N_NODES) {
            float4 o;
            o.x = fmaxf(hi[0] + bv.x, 0.f);
            o.y = fmaxf(hi[1] + bv.y, 0.f);
            o.z = fmaxf(hi[2] + bv.z, 0.f);
            o.w = fmaxf(hi[3] + bv.w, 0.f);
            reinterpret_cast<float4*>(out)[(size_t)(r0 + 1) * D4 + lane] = o;
        }
    }
}

// ---------------------------------------------------------------------------
// Inputs: feature f32[50000,128], edge_src i32[800000], edge_dst i32[800000],
// W f32[128,128], b f32[128]. Output f32[50000,128].
// ---------------------------------------------------------------------------
extern "C" void kernel_launch(void* const* d_in, const int* in_sizes, int n_in,
                              void* d_out, int out_size) {
    const float* feature  = (const float*)d_in[0];
    const int*   edge_src = (const int*)d_in[1];
    const int*   edge_dst = (const int*)d_in[2];
    const float* W        = (const float*)d_in[3];
    const float* b        = (const float*)d_in[4];
    float* out = (float*)d_out;

    prep_kernel<<<(N_NODES * D4 + 255) / 256, 256>>>(feature);
    hist_kernel<<<(N_EDGES / 4 + 255) / 256, 256>>>(edge_dst);
    scan1_kernel<<<N_BLKS, SCAN_B>>>();
    scan2_kernel<<<1, 64>>>();
    scan3_kernel<<<N_BLKS, SCAN_B>>>();
    bucket_kernel<<<(N_EDGES / 4 + 255) / 256, 256>>>(edge_src, edge_dst);
    agg_kernel<<<(N_NODES * 32 + 255) / 256, 256>>>();
    gemm_kernel<<<(N_NODES + 63) / 64, 256>>>(W, b, out);
}

// round 8
// speedup vs baseline: 4.0354x; 1.6592x over previous
#include <cuda_runtime.h>
#include <cuda_fp16.h>
#include <cstdint>

#define N_NODES 50000
#define N_EDGES 800000
#define D 128
#define D4 (D / 4)
#define FULL 0xffffffffu
#define SCAN_B 1024
#define N_BLKS ((N_NODES + SCAN_B - 1) / SCAN_B)   // 49

// Static device scratch (no allocation; zero-initialized at load).
__device__ int   g_deg[N_NODES];
__device__ int   g_off[N_NODES + 1];
__device__ int   g_cursor[N_NODES];
__device__ int   g_csr[N_EDGES];
__device__ int   g_blk[64];                  // per-block scan sums
__device__ uint4 g_feat_h[N_NODES * 16];     // fp16 feature: row = 256B = 16 uint4
__device__ uint4 g_hh[N_NODES * 16];         // fp16 aggregate h (row = 256B)
__device__ uint2 g_Wh[D * D / 4];            // fp16 W, row-major [k][n]
__device__ uint4 g_zero16[16];               // 256B of zeros, never written

// ---------------------------------------------------------------------------
// K1: prep — feature f32->f16, W f32->f16, AND in-degree histogram.
// g_deg was cleared by the PREVIOUS execution's gemm kernel (zero at load).
// ---------------------------------------------------------------------------
__global__ void __launch_bounds__(256) prep_kernel(const float* __restrict__ feature,
                                                   const float* __restrict__ W,
                                                   const int* __restrict__ edge_dst) {
    int i = blockIdx.x * blockDim.x + threadIdx.x;
    if (i < N_NODES * D4) {
        float4 v = __ldg(reinterpret_cast<const float4*>(feature) + i);
        __half2 lo = __floats2half2_rn(v.x, v.y);
        __half2 hi = __floats2half2_rn(v.z, v.w);
        uint2 p;
        p.x = *reinterpret_cast<unsigned*>(&lo);
        p.y = *reinterpret_cast<unsigned*>(&hi);
        reinterpret_cast<uint2*>(g_feat_h)[i] = p;
    }
    if (i < D * D / 4) {
        float4 v = __ldg(reinterpret_cast<const float4*>(W) + i);
        __half2 lo = __floats2half2_rn(v.x, v.y);
        __half2 hi = __floats2half2_rn(v.z, v.w);
        uint2 p;
        p.x = *reinterpret_cast<unsigned*>(&lo);
        p.y = *reinterpret_cast<unsigned*>(&hi);
        g_Wh[i] = p;
    }
    if (i < N_EDGES / 4) {
        int4 d = __ldg(reinterpret_cast<const int4*>(edge_dst) + i);
        atomicAdd(&g_deg[d.x], 1);
        atomicAdd(&g_deg[d.y], 1);
        atomicAdd(&g_deg[d.z], 1);
        atomicAdd(&g_deg[d.w], 1);
    }
}

// ---------------------------------------------------------------------------
// K2: per-block exclusive scan (coalesced). Block total -> g_blk.
// ---------------------------------------------------------------------------
__global__ void __launch_bounds__(SCAN_B) scan1_kernel() {
    __shared__ int s_wsum[32];
    int t = threadIdx.x, wid = t >> 5, lane = t & 31;
    int i = blockIdx.x * SCAN_B + t;
    int v = (i < N_NODES) ? g_deg[i] : 0;

    int x = v;
    #pragma unroll
    for (int d = 1; d < 32; d <<= 1) {
        int y = __shfl_up_sync(FULL, x, d);
        if (lane >= d) x += y;
    }
    if (lane == 31) s_wsum[wid] = x;
    __syncthreads();
    if (wid == 0) {
        int w = s_wsum[lane];
        int xx = w;
        #pragma unroll
        for (int d = 1; d < 32; d <<= 1) {
            int y = __shfl_up_sync(FULL, xx, d);
            if (lane >= d) xx += y;
        }
        s_wsum[lane] = xx - w;
        if (lane == 31) g_blk[blockIdx.x] = xx;
    }
    __syncthreads();

    if (i < N_NODES) g_off[i] = (x - v) + s_wsum[wid];
}

// ---------------------------------------------------------------------------
// K3: add block offsets + init cursors. Each block computes its own prefix of
// the 49 block totals with one warp (kills the separate scan2 launch).
// ---------------------------------------------------------------------------
__global__ void __launch_bounds__(SCAN_B) scan3_kernel() {
    __shared__ int s_off;
    int t = threadIdx.x;
    if (t < 32) {
        int v = 0;
        if (t < (int)blockIdx.x) v = g_blk[t];
        if (t + 32 < (int)blockIdx.x) v += g_blk[t + 32];
        #pragma unroll
        for (int d = 16; d >= 1; d >>= 1) v += __shfl_xor_sync(FULL, v, d);
        if (t == 0) s_off = v;
    }
    __syncthreads();

    int i = blockIdx.x * SCAN_B + t;
    if (i < N_NODES) {
        int off = g_off[i] + s_off;
        g_off[i] = off;
        g_cursor[i] = off;
    }
    if (i == 0) g_off[N_NODES] = N_EDGES;
}

// ---------------------------------------------------------------------------
// K4: bucket fill.
// ---------------------------------------------------------------------------
__global__ void bucket_kernel(const int* __restrict__ edge_src,
                              const int* __restrict__ edge_dst) {
    int i = blockIdx.x * blockDim.x + threadIdx.x;
    if (i < N_EDGES / 4) {
        int4 d = reinterpret_cast<const int4*>(edge_dst)[i];
        int4 s = reinterpret_cast<const int4*>(edge_src)[i];
        g_csr[atomicAdd(&g_cursor[d.x], 1)] = s.x;
        g_csr[atomicAdd(&g_cursor[d.y], 1)] = s.y;
        g_csr[atomicAdd(&g_cursor[d.z], 1)] = s.z;
        g_csr[atomicAdd(&g_cursor[d.w], 1)] = s.w;
    }
}

// ---------------------------------------------------------------------------
// K5: aggregate — one warp per node, half-warp per gathered fp16 row.
// Accumulate fp32, write h as fp16 (halves write traffic; GEMM wants fp16).
// ---------------------------------------------------------------------------
__device__ __forceinline__ void acc8(float* acc, uint4 a) {
    float2 f0 = __half22float2(*reinterpret_cast<__half2*>(&a.x));
    float2 f1 = __half22float2(*reinterpret_cast<__half2*>(&a.y));
    float2 f2 = __half22float2(*reinterpret_cast<__half2*>(&a.z));
    float2 f3 = __half22float2(*reinterpret_cast<__half2*>(&a.w));
    acc[0] += f0.x; acc[1] += f0.y; acc[2] += f1.x; acc[3] += f1.y;
    acc[4] += f2.x; acc[5] += f2.y; acc[6] += f3.x; acc[7] += f3.y;
}

__global__ void __launch_bounds__(256) agg_kernel() {
    int w = (blockIdx.x * blockDim.x + threadIdx.x) >> 5;
    int lane = threadIdx.x & 31;
    if (w >= N_NODES) return;
    int half = lane >> 4;
    int hl   = lane & 15;

    int j0 = g_off[w];
    int len = g_off[w + 1] - j0;

    const uint4* fh = g_feat_h;
    float acc[8];
    #pragma unroll
    for (int i = 0; i < 8; i++) acc[i] = 0.f;

    for (int base = 0; base < len; base += 32) {
        int nb = len - base; if (nb > 32) nb = 32;
        int myidx = 0;
        if (base + lane < len) myidx = g_csr[j0 + base + lane];

        int t = 0;
        for (; t + 8 <= nb; t += 8) {
            int s0 = __shfl_sync(FULL, myidx, t + 0 + half);
            int s1 = __shfl_sync(FULL, myidx, t + 2 + half);
            int s2 = __shfl_sync(FULL, myidx, t + 4 + half);
            int s3 = __shfl_sync(FULL, myidx, t + 6 + half);
            uint4 a0 = __ldg(fh + (size_t)s0 * 16 + hl);
            uint4 a1 = __ldg(fh + (size_t)s1 * 16 + hl);
            uint4 a2 = __ldg(fh + (size_t)s2 * 16 + hl);
            uint4 a3 = __ldg(fh + (size_t)s3 * 16 + hl);
            acc8(acc, a0); acc8(acc, a1); acc8(acc, a2); acc8(acc, a3);
        }
        for (; t + 2 <= nb; t += 2) {
            int s0 = __shfl_sync(FULL, myidx, t + half);
            uint4 a0 = __ldg(fh + (size_t)s0 * 16 + hl);
            acc8(acc, a0);
        }
        if (t < nb) {
            int s0 = __shfl_sync(FULL, myidx, t);
            const uint4* p = half ? (const uint4*)g_zero16 : (fh + (size_t)s0 * 16);
            uint4 a0 = __ldg(p + hl);
            acc8(acc, a0);
        }
    }

    #pragma unroll
    for (int i = 0; i < 8; i++)
        acc[i] += __shfl_xor_sync(FULL, acc[i], 16);

    if (half == 0) {
        __half2 h0 = __floats2half2_rn(acc[0], acc[1]);
        __half2 h1 = __floats2half2_rn(acc[2], acc[3]);
        __half2 h2 = __floats2half2_rn(acc[4], acc[5]);
        __half2 h3 = __floats2half2_rn(acc[6], acc[7]);
        uint4 p;
        p.x = *reinterpret_cast<unsigned*>(&h0);
        p.y = *reinterpret_cast<unsigned*>(&h1);
        p.z = *reinterpret_cast<unsigned*>(&h2);
        p.w = *reinterpret_cast<unsigned*>(&h3);
        g_hh[(size_t)w * 16 + hl] = p;
    }
}

// ---------------------------------------------------------------------------
// K6: out = relu(h @ W + b) via tensor cores (mma.m16n8k16 f16f16->f32).
// Block = 256 thr = 8 warps = 4 m-groups(16 rows) x 2 n-groups(64 cols);
// block covers 64 rows. h tile (64x128 f16) + W (128x128 f16) in smem with
// XOR swizzle (unit ^ (row&7)) for conflict-free ldmatrix. Also clears g_deg
// for the NEXT execution's histogram.
// ---------------------------------------------------------------------------
__global__ void __launch_bounds__(256) gemm_kernel(const float* __restrict__ b,
                                                   float* __restrict__ out) {
    __shared__ uint4 sW[D * 16];    // 32 KB, row k: 16 units
    __shared__ uint4 sA[64 * 16];   // 16 KB, 64 h rows

    int tid = threadIdx.x;
    int warp = tid >> 5;
    int lane = tid & 31;
    int warp_m = warp >> 1;          // 0..3
    int warp_n = warp & 1;           // 0..1
    int row0 = blockIdx.x * 64;

    // Clear g_deg for next execution's histogram (stream order guarantees
    // this lands before the next prep_kernel runs).
    {
        int gid = blockIdx.x * 256 + tid;
        if (gid < N_NODES) g_deg[gid] = 0;
    }

    // Stage W: 2048 units of 16B.
    #pragma unroll
    for (int it = 0; it < 8; it++) {
        int seg = tid + it * 256;
        int row = seg >> 4, u = seg & 15;
        sW[row * 16 + (u ^ (row & 7))] = reinterpret_cast<const uint4*>(g_Wh)[seg];
    }
    // Stage h tile: 1024 units.
    #pragma unroll
    for (int it = 0; it < 4; it++) {
        int seg = tid + it * 256;
        int r = seg >> 4, u = seg & 15;
        int grow = row0 + r;
        uint4 v = make_uint4(0u, 0u, 0u, 0u);
        if (grow < N_NODES) v = g_hh[(size_t)grow * 16 + u];
        sA[r * 16 + (u ^ (r & 7))] = v;
    }
    __syncthreads();

    unsigned sWb = (unsigned)__cvta_generic_to_shared(sW);
    unsigned sAb = (unsigned)__cvta_generic_to_shared(sA);

    float d[8][4];
    #pragma unroll
    for (int t = 0; t < 8; t++)
        #pragma unroll
        for (int c = 0; c < 4; c++) d[t][c] = 0.f;

    int lt = lane >> 3;   // ldmatrix tile group 0..3
    int lj = lane & 7;

    #pragma unroll
    for (int k = 0; k < 8; k++) {
        // A fragment: m16 x k16 at (warp_m*16, k*16).
        unsigned a0, a1, a2, a3;
        {
            int rr = warp_m * 16 + ((lt & 1) << 3) + lj;
            int u  = (k << 1) + (lt >> 1);
            unsigned addr = sAb + ((rr << 4) + (u ^ (rr & 7))) * 16;
            asm volatile("ldmatrix.sync.aligned.m8n8.x4.shared.b16 {%0,%1,%2,%3}, [%4];"
                         : "=r"(a0), "=r"(a1), "=r"(a2), "=r"(a3) : "r"(addr));
        }
        // B fragments: 4 x (x4.trans) covering 8 n-tiles of 8 cols.
        #pragma unroll
        for (int p = 0; p < 4; p++) {
            int n0 = warp_n * 64 + p * 16;
            int rr = (k << 4) + ((lt & 1) << 3) + lj;
            int u  = (n0 >> 3) + (lt >> 1);
            unsigned addr = sWb + ((rr << 4) + (u ^ (rr & 7))) * 16;
            unsigned b00, b01, b10, b11;
            asm volatile("ldmatrix.sync.aligned.m8n8.x4.trans.shared.b16 {%0,%1,%2,%3}, [%4];"
                         : "=r"(b00), "=r"(b01), "=r"(b10), "=r"(b11) : "r"(addr));
            int t0 = 2 * p, t1 = 2 * p + 1;
            asm volatile("mma.sync.aligned.m16n8k16.row.col.f32.f16.f16.f32 "
                         "{%0,%1,%2,%3}, {%4,%5,%6,%7}, {%8,%9}, {%0,%1,%2,%3};"
                         : "+f"(d[t0][0]), "+f"(d[t0][1]), "+f"(d[t0][2]), "+f"(d[t0][3])
                         : "r"(a0), "r"(a1), "r"(a2), "r"(a3), "r"(b00), "r"(b01));
            asm volatile("mma.sync.aligned.m16n8k16.row.col.f32.f16.f16.f32 "
                         "{%0,%1,%2,%3}, {%4,%5,%6,%7}, {%8,%9}, {%0,%1,%2,%3};"
                         : "+f"(d[t1][0]), "+f"(d[t1][1]), "+f"(d[t1][2]), "+f"(d[t1][3])
                         : "r"(a0), "r"(a1), "r"(a2), "r"(a3), "r"(b10), "r"(b11));
        }
    }

    // Epilogue: bias + relu + f32 stores.
    int r = lane >> 2;
    int c = (lane & 3) * 2;
    #pragma unroll
    for (int t = 0; t < 8; t++) {
        int col = warp_n * 64 + t * 8 + c;
        float2 bb = *reinterpret_cast<const float2*>(b + col);
        int grow = row0 + warp_m * 16 + r;
        if (grow < N_NODES) {
            float2 o;
            o.x = fmaxf(d[t][0] + bb.x, 0.f);
            o.y = fmaxf(d[t][1] + bb.y, 0.f);
            *reinterpret_cast<float2*>(out + (size_t)grow * D + col) = o;
        }
        int grow2 = grow + 8;
        if (grow2 < N_NODES) {
            float2 o;
            o.x = fmaxf(d[t][2] + bb.x, 0.f);
            o.y = fmaxf(d[t][3] + bb.y, 0.f);
            *reinterpret_cast<float2*>(out + (size_t)grow2 * D + col) = o;
        }
    }
}

// ---------------------------------------------------------------------------
// Inputs: feature f32[50000,128], edge_src i32[800000], edge_dst i32[800000],
// W f32[128,128], b f32[128]. Output f32[50000,128].
// ---------------------------------------------------------------------------
extern "C" void kernel_launch(void* const* d_in, const int* in_sizes, int n_in,
                              void* d_out, int out_size) {
    const float* feature  = (const float*)d_in[0];
    const int*   edge_src = (const int*)d_in[1];
    const int*   edge_dst = (const int*)d_in[2];
    const float* W        = (const float*)d_in[3];
    const float* b        = (const float*)d_in[4];
    float* out = (float*)d_out;

    prep_kernel<<<(N_NODES * D4 + 255) / 256, 256>>>(feature, W, edge_dst);
    scan1_kernel<<<N_BLKS, SCAN_B>>>();
    scan3_kernel<<<N_BLKS, SCAN_B>>>();
    bucket_kernel<<<(N_EDGES / 4 + 255) / 256, 256>>>(edge_src, edge_dst);
    agg_kernel<<<(N_NODES * 32 + 255) / 256, 256>>>();
    gemm_kernel<<<(N_NODES + 63) / 64, 256>>>(b, out);
}